// round 7
// baseline (speedup 1.0000x reference)
#include <cuda_runtime.h>
#include <cuda_bf16.h>
#include <cstdint>
#include <math.h>

// Problem constants
#define S_LEN  2048
#define DMODEL 4096
#define HQ     32
#define HKV    8
#define HD     128
#define DKV    (HKV * HD)   // 1024

// ---------------------------------------------------------------------------
// Scratch (device globals)
// ---------------------------------------------------------------------------
__device__ float g_q[(size_t)S_LEN * DMODEL];       // fp32 Q projection
__device__ float g_k[(size_t)S_LEN * DKV];          // fp32 K projection
__device__ float g_v[(size_t)S_LEN * DKV];          // fp32 V projection
__device__ float g_attn[(size_t)S_LEN * DMODEL];    // fp32 PV result
__device__ float g_scores[(size_t)HQ * S_LEN * S_LEN];

// bf16 hi/lo split operands
__device__ __nv_bfloat16 g_xh[(size_t)S_LEN * DMODEL],  g_xl[(size_t)S_LEN * DMODEL];
__device__ __nv_bfloat16 g_wqh[(size_t)DMODEL * DMODEL], g_wql[(size_t)DMODEL * DMODEL];
__device__ __nv_bfloat16 g_wkh[(size_t)DKV * DMODEL],    g_wkl[(size_t)DKV * DMODEL];
__device__ __nv_bfloat16 g_wvh[(size_t)DKV * DMODEL],    g_wvl[(size_t)DKV * DMODEL];
__device__ __nv_bfloat16 g_woh[(size_t)DMODEL * DMODEL], g_wol[(size_t)DMODEL * DMODEL];
__device__ __nv_bfloat16 g_qh[(size_t)S_LEN * DMODEL],   g_ql[(size_t)S_LEN * DMODEL];
__device__ __nv_bfloat16 g_kh[(size_t)S_LEN * DKV],      g_kl[(size_t)S_LEN * DKV];
__device__ __nv_bfloat16 g_vth[(size_t)DKV * S_LEN],     g_vtl[(size_t)DKV * S_LEN];
__device__ __nv_bfloat16 g_ph[(size_t)HQ * S_LEN * S_LEN], g_pl[(size_t)HQ * S_LEN * S_LEN];
__device__ __nv_bfloat16 g_ah[(size_t)S_LEN * DMODEL],   g_al[(size_t)S_LEN * DMODEL];

// ---------------------------------------------------------------------------
// PTX helpers
// ---------------------------------------------------------------------------
__device__ __forceinline__ uint32_t smem_u32(const void* p) {
    uint32_t a;
    asm("{ .reg .u64 t; cvta.to.shared.u64 t, %1; cvt.u32.u64 %0, t; }"
        : "=r"(a) : "l"(p));
    return a;
}
__device__ __forceinline__ void ldsm_x4(uint32_t r[4], uint32_t addr) {
    asm volatile("ldmatrix.sync.aligned.m8n8.x4.shared.b16 {%0,%1,%2,%3}, [%4];"
        : "=r"(r[0]), "=r"(r[1]), "=r"(r[2]), "=r"(r[3]) : "r"(addr));
}
__device__ __forceinline__ void ldsm_x2(uint32_t r[2], uint32_t addr) {
    asm volatile("ldmatrix.sync.aligned.m8n8.x2.shared.b16 {%0,%1}, [%2];"
        : "=r"(r[0]), "=r"(r[1]) : "r"(addr));
}
__device__ __forceinline__ void mma_bf16(float d[4], const uint32_t a[4],
                                         const uint32_t b[2]) {
    asm volatile(
        "mma.sync.aligned.m16n8k16.row.col.f32.bf16.bf16.f32 "
        "{%0,%1,%2,%3}, {%4,%5,%6,%7}, {%8,%9}, {%0,%1,%2,%3};"
        : "+f"(d[0]), "+f"(d[1]), "+f"(d[2]), "+f"(d[3])
        : "r"(a[0]), "r"(a[1]), "r"(a[2]), "r"(a[3]), "r"(b[0]), "r"(b[1]));
}
#define CP_ASYNC16(sm_addr, gptr) \
    asm volatile("cp.async.cg.shared.global [%0], [%1], 16;" \
                 :: "r"(sm_addr), "l"(gptr) : "memory")
#define CP_COMMIT() asm volatile("cp.async.commit_group;" ::: "memory")
#define CP_WAIT0()  asm volatile("cp.async.wait_group 0;" ::: "memory")

__device__ __forceinline__ void split2(float x, __nv_bfloat16& h, __nv_bfloat16& l) {
    h = __float2bfloat16(x);
    l = __float2bfloat16(x - __bfloat162float(h));
}

// ---------------------------------------------------------------------------
// bf16-split tensor-core GEMM NT with cp.async double-buffer:
//   C[M,N] = alpha * (Ah+Al)[M,K] * (Bh+Bl)[N,K]^T   (row-major, K contig)
// Tile 128x128, K-step 32, 256 threads (8 warps: 2 over M x 4 over N).
// Batched over blockIdx.z; B index = z / bdivB (GQA map).
// ---------------------------------------------------------------------------
#define BPITCH 40                 // smem pitch in bf16 (80 bytes)
#define TILE_B (128 * 80)         // 10240 B per tile
#define STAGE_B (4 * TILE_B)      // Ah, Al, Bh, Bl per stage
#define GSMEM  (2 * STAGE_B)      // 81920 B

__global__ __launch_bounds__(256) void tcg_nt(
    const __nv_bfloat16* __restrict__ Ah, const __nv_bfloat16* __restrict__ Al,
    const __nv_bfloat16* __restrict__ Bh, const __nv_bfloat16* __restrict__ Bl,
    float* __restrict__ C, int K, int lda, int ldb, int ldc,
    long long strA, long long strB, long long strC, int bdivB, float alpha)
{
    extern __shared__ char smem[];
    const uint32_t sbase = smem_u32(smem);

    const long long za = (long long)blockIdx.z * strA;
    const long long zb = (long long)(blockIdx.z / bdivB) * strB;
    Ah += za; Al += za; Bh += zb; Bl += zb;
    C  += (long long)blockIdx.z * strC;

    const int row0 = blockIdx.y * 128;
    const int col0 = blockIdx.x * 128;
    const int tid  = threadIdx.x;
    const int lane = tid & 31;
    const int w    = tid >> 5;
    const int wm   = (w & 1) * 64;
    const int wn   = (w >> 1) * 32;

    // prefetch thread mapping: idx in [0,512): r=idx>>2 (row), c=(idx&3)*8 (bf16 col)
    const int pr  = (tid << 1) >> 2;          // rows for the 2 chunks
    const int pr1 = ((tid << 1) + 1) >> 2;
    const int pc  = ((tid << 1) & 3) * 8;
    const int pc1 = (((tid << 1) + 1) & 3) * 8;

    float acc[4][4][4];
#pragma unroll
    for (int i = 0; i < 4; i++)
#pragma unroll
        for (int j = 0; j < 4; j++)
#pragma unroll
            for (int e = 0; e < 4; e++) acc[i][j][e] = 0.f;

    const int KT = K / 32;

#define PREFETCH(kt, stage) do {                                               \
    const int k0 = (kt) * 32;                                                  \
    const uint32_t ss = sbase + (stage) * STAGE_B;                             \
    uint32_t o0 = (uint32_t)(pr  * 80 + pc  * 2);                              \
    uint32_t o1 = (uint32_t)(pr1 * 80 + pc1 * 2);                              \
    CP_ASYNC16(ss + o0,              Ah + (long long)(row0 + pr ) * lda + k0 + pc ); \
    CP_ASYNC16(ss + o1,              Ah + (long long)(row0 + pr1) * lda + k0 + pc1); \
    CP_ASYNC16(ss + TILE_B + o0,     Al + (long long)(row0 + pr ) * lda + k0 + pc ); \
    CP_ASYNC16(ss + TILE_B + o1,     Al + (long long)(row0 + pr1) * lda + k0 + pc1); \
    CP_ASYNC16(ss + 2 * TILE_B + o0, Bh + (long long)(col0 + pr ) * ldb + k0 + pc ); \
    CP_ASYNC16(ss + 2 * TILE_B + o1, Bh + (long long)(col0 + pr1) * ldb + k0 + pc1); \
    CP_ASYNC16(ss + 3 * TILE_B + o0, Bl + (long long)(col0 + pr ) * ldb + k0 + pc ); \
    CP_ASYNC16(ss + 3 * TILE_B + o1, Bl + (long long)(col0 + pr1) * ldb + k0 + pc1); \
} while (0)

    PREFETCH(0, 0);
    CP_COMMIT();

    for (int kt = 0; kt < KT; kt++) {
        CP_WAIT0();
        __syncthreads();
        if (kt + 1 < KT) {
            PREFETCH(kt + 1, (kt + 1) & 1);
            CP_COMMIT();
        }
        const uint32_t ss = sbase + (kt & 1) * STAGE_B;
        const uint32_t ah0 = ss, al0 = ss + TILE_B;
        const uint32_t bh0 = ss + 2 * TILE_B, bl0 = ss + 3 * TILE_B;

#pragma unroll
        for (int kc = 0; kc < 2; kc++) {
            const int kb = kc * 16;
            uint32_t afh[4][4], afl[4][4], bfh[4][2], bfl[4][2];
            {
                int rr = lane & 15;
                int cc = kb + ((lane >> 4) << 3);
#pragma unroll
                for (int mi = 0; mi < 4; mi++) {
                    uint32_t off = (uint32_t)((wm + mi * 16 + rr) * 80 + cc * 2);
                    ldsm_x4(afh[mi], ah0 + off);
                    ldsm_x4(afl[mi], al0 + off);
                }
            }
            {
                int rr = lane & 7;
                int cc = kb + (((lane >> 3) & 1) << 3);
#pragma unroll
                for (int nj = 0; nj < 4; nj++) {
                    uint32_t off = (uint32_t)((wn + nj * 8 + rr) * 80 + cc * 2);
                    ldsm_x2(bfh[nj], bh0 + off);
                    ldsm_x2(bfl[nj], bl0 + off);
                }
            }
#pragma unroll
            for (int mi = 0; mi < 4; mi++)
#pragma unroll
                for (int nj = 0; nj < 4; nj++) {
                    mma_bf16(acc[mi][nj], afh[mi], bfh[nj]);
                    mma_bf16(acc[mi][nj], afh[mi], bfl[nj]);
                    mma_bf16(acc[mi][nj], afl[mi], bfh[nj]);
                }
        }
        __syncthreads();
    }
#undef PREFETCH

    // store
#pragma unroll
    for (int mi = 0; mi < 4; mi++)
#pragma unroll
        for (int nj = 0; nj < 4; nj++) {
            int r = row0 + wm + mi * 16 + (lane >> 2);
            int c = col0 + wn + nj * 8 + (lane & 3) * 2;
            float* p0 = C + (long long)r * ldc + c;
            p0[0] = acc[mi][nj][0] * alpha;
            p0[1] = acc[mi][nj][1] * alpha;
            float* p1 = C + (long long)(r + 8) * ldc + c;
            p1[0] = acc[mi][nj][2] * alpha;
            p1[1] = acc[mi][nj][3] * alpha;
        }
}

// ---------------------------------------------------------------------------
// Elementwise split: fp32 -> bf16 hi/lo (n must be multiple of 4)
// ---------------------------------------------------------------------------
__global__ void split_f32(const float* __restrict__ in,
                          __nv_bfloat16* __restrict__ hi,
                          __nv_bfloat16* __restrict__ lo, long long n)
{
    long long i4 = ((long long)blockIdx.x * blockDim.x + threadIdx.x) * 4;
    if (i4 >= n) return;
    float4 v = *(const float4*)(in + i4);
    __nv_bfloat16 h0, h1, h2, h3, l0, l1, l2, l3;
    split2(v.x, h0, l0); split2(v.y, h1, l1);
    split2(v.z, h2, l2); split2(v.w, h3, l3);
    __nv_bfloat162 hh0 = __halves2bfloat162(h0, h1);
    __nv_bfloat162 hh1 = __halves2bfloat162(h2, h3);
    __nv_bfloat162 ll0 = __halves2bfloat162(l0, l1);
    __nv_bfloat162 ll1 = __halves2bfloat162(l2, l3);
    *(uint2*)(hi + i4) = make_uint2(*(uint32_t*)&hh0, *(uint32_t*)&hh1);
    *(uint2*)(lo + i4) = make_uint2(*(uint32_t*)&ll0, *(uint32_t*)&ll1);
}

// ---------------------------------------------------------------------------
// RoPE: read fp32 g_q/g_k, rotate, write bf16 hi/lo directly
// ---------------------------------------------------------------------------
__global__ void rope_split() {
    long long idx = (long long)blockIdx.x * blockDim.x + threadIdx.x;
    const long long QP = (long long)S_LEN * HQ * 64;
    const long long KP = (long long)S_LEN * HKV * 64;
    if (idx >= QP + KP) return;

    const float* src; __nv_bfloat16 *dh, *dl;
    int s, h, i, stride;
    if (idx < QP) {
        s = (int)(idx / (HQ * 64));
        int rem = (int)(idx % (HQ * 64));
        h = rem / 64; i = rem % 64;
        src = g_q; dh = g_qh; dl = g_ql; stride = DMODEL;
    } else {
        long long t = idx - QP;
        s = (int)(t / (HKV * 64));
        int rem = (int)(t % (HKV * 64));
        h = rem / 64; i = rem % 64;
        src = g_k; dh = g_kh; dl = g_kl; stride = DKV;
    }

    float invf = (float)(1.0 / pow(10000.0, (double)i / 64.0));
    float ang = (float)s * invf;
    double sd, cd;
    sincos((double)ang, &sd, &cd);
    float c = (float)cd, sn = (float)sd;

    size_t off = (size_t)s * (size_t)stride + (size_t)h * HD + 2 * (size_t)i;
    float x1 = src[off], x2 = src[off + 1];
    float o1 = x1 * c - x2 * sn;
    float o2 = x1 * sn + x2 * c;
    __nv_bfloat16 h1, h2, l1, l2;
    split2(o1, h1, l1); split2(o2, h2, l2);
    __nv_bfloat162 hv = __halves2bfloat162(h1, h2);
    __nv_bfloat162 lv = __halves2bfloat162(l1, l2);
    *(uint32_t*)(dh + off) = *(uint32_t*)&hv;
    *(uint32_t*)(dl + off) = *(uint32_t*)&lv;
}

// ---------------------------------------------------------------------------
// Transpose V [s][d] -> Vt [d][s], bf16 hi/lo output
// ---------------------------------------------------------------------------
__global__ void transpose_v_split() {
    __shared__ float t[32][33];
    int d0 = blockIdx.x * 32;
    int s0 = blockIdx.y * 32;
    for (int i = threadIdx.y; i < 32; i += 8)
        t[i][threadIdx.x] = g_v[(size_t)(s0 + i) * DKV + d0 + threadIdx.x];
    __syncthreads();
    for (int i = threadIdx.y; i < 32; i += 8) {
        float v = t[threadIdx.x][i];
        __nv_bfloat16 h, l;
        split2(v, h, l);
        size_t o = (size_t)(d0 + i) * S_LEN + s0 + threadIdx.x;
        g_vth[o] = h;
        g_vtl[o] = l;
    }
}

// ---------------------------------------------------------------------------
// Softmax: fp32 scores in, bf16 hi/lo P out. One warp per row.
// ---------------------------------------------------------------------------
__global__ __launch_bounds__(256) void softmax_split() {
    const int row = blockIdx.x * 8 + (threadIdx.x >> 5);
    const int l   = threadIdx.x & 31;
    const float* p = g_scores + (size_t)row * S_LEN;
    __nv_bfloat16* ph = g_ph + (size_t)row * S_LEN;
    __nv_bfloat16* pl = g_pl + (size_t)row * S_LEN;

    float vals[64];
    float m = -3.0e38f;
#pragma unroll
    for (int i = 0; i < 64; i++) {
        vals[i] = p[l + 32 * i];
        m = fmaxf(m, vals[i]);
    }
#pragma unroll
    for (int o = 16; o > 0; o >>= 1)
        m = fmaxf(m, __shfl_xor_sync(0xffffffffu, m, o));

    float s = 0.f;
#pragma unroll
    for (int i = 0; i < 64; i++) {
        vals[i] = expf(vals[i] - m);
        s += vals[i];
    }
#pragma unroll
    for (int o = 16; o > 0; o >>= 1)
        s += __shfl_xor_sync(0xffffffffu, s, o);

    float inv = 1.0f / s;
#pragma unroll
    for (int i = 0; i < 64; i++) {
        float v = vals[i] * inv;
        __nv_bfloat16 h, lo;
        split2(v, h, lo);
        ph[l + 32 * i] = h;
        pl[l + 32 * i] = lo;
    }
}

// ---------------------------------------------------------------------------
// Launch
// ---------------------------------------------------------------------------
extern "C" void kernel_launch(void* const* d_in, const int* in_sizes, int n_in,
                              void* d_out, int out_size)
{
    const float* x  = (const float*)d_in[0];
    const float* wq = (const float*)d_in[1];
    const float* wk = (const float*)d_in[2];
    const float* wv = (const float*)d_in[3];
    const float* wo = (const float*)d_in[4];
    float* out = (float*)d_out;

    float *q, *k, *v, *attn, *sc;
    cudaGetSymbolAddress((void**)&q,    g_q);
    cudaGetSymbolAddress((void**)&k,    g_k);
    cudaGetSymbolAddress((void**)&v,    g_v);
    cudaGetSymbolAddress((void**)&attn, g_attn);
    cudaGetSymbolAddress((void**)&sc,   g_scores);

    __nv_bfloat16 *xh, *xl, *wqh, *wql, *wkh, *wkl, *wvh, *wvl, *woh, *wol;
    __nv_bfloat16 *qh, *ql, *kh, *kl, *vth, *vtl, *ph, *pl, *ah, *al;
    cudaGetSymbolAddress((void**)&xh,  g_xh);  cudaGetSymbolAddress((void**)&xl,  g_xl);
    cudaGetSymbolAddress((void**)&wqh, g_wqh); cudaGetSymbolAddress((void**)&wql, g_wql);
    cudaGetSymbolAddress((void**)&wkh, g_wkh); cudaGetSymbolAddress((void**)&wkl, g_wkl);
    cudaGetSymbolAddress((void**)&wvh, g_wvh); cudaGetSymbolAddress((void**)&wvl, g_wvl);
    cudaGetSymbolAddress((void**)&woh, g_woh); cudaGetSymbolAddress((void**)&wol, g_wol);
    cudaGetSymbolAddress((void**)&qh,  g_qh);  cudaGetSymbolAddress((void**)&ql,  g_ql);
    cudaGetSymbolAddress((void**)&kh,  g_kh);  cudaGetSymbolAddress((void**)&kl,  g_kl);
    cudaGetSymbolAddress((void**)&vth, g_vth); cudaGetSymbolAddress((void**)&vtl, g_vtl);
    cudaGetSymbolAddress((void**)&ph,  g_ph);  cudaGetSymbolAddress((void**)&pl,  g_pl);
    cudaGetSymbolAddress((void**)&ah,  g_ah);  cudaGetSymbolAddress((void**)&al,  g_al);

    cudaFuncSetAttribute(tcg_nt,
        cudaFuncAttributeMaxDynamicSharedMemorySize, GSMEM);

    const float scale = 0.08838834764831845f;  // 1/sqrt(128)

#define SPLIT(src, h, l, n) \
    split_f32<<<(int)(((n) / 4 + 255) / 256), 256>>>(src, h, l, (long long)(n))

    // 0) split inputs
    SPLIT(x,  xh,  xl,  (long long)S_LEN * DMODEL);
    SPLIT(wq, wqh, wql, (long long)DMODEL * DMODEL);
    SPLIT(wk, wkh, wkl, (long long)DKV * DMODEL);
    SPLIT(wv, wvh, wvl, (long long)DKV * DMODEL);
    SPLIT(wo, woh, wol, (long long)DMODEL * DMODEL);

    // 1) Projections (fp32 out)
    tcg_nt<<<dim3(DMODEL / 128, S_LEN / 128, 1), 256, GSMEM>>>(
        xh, xl, wqh, wql, q, DMODEL, DMODEL, DMODEL, DMODEL, 0, 0, 0, 1, 1.0f);
    tcg_nt<<<dim3(DKV / 128, S_LEN / 128, 1), 256, GSMEM>>>(
        xh, xl, wkh, wkl, k, DMODEL, DMODEL, DMODEL, DKV, 0, 0, 0, 1, 1.0f);
    tcg_nt<<<dim3(DKV / 128, S_LEN / 128, 1), 256, GSMEM>>>(
        xh, xl, wvh, wvl, v, DMODEL, DMODEL, DMODEL, DKV, 0, 0, 0, 1, 1.0f);

    // 2) RoPE -> bf16 hi/lo Q, K
    {
        long long total = (long long)S_LEN * HQ * 64 + (long long)S_LEN * HKV * 64;
        rope_split<<<(int)((total + 255) / 256), 256>>>();
    }

    // 3) V transpose -> bf16 hi/lo Vt
    transpose_v_split<<<dim3(DKV / 32, S_LEN / 32), dim3(32, 8)>>>();

    // 4) scores[h] = scale * Q_h K_{h/4}^T (fp32 out)
    tcg_nt<<<dim3(S_LEN / 128, S_LEN / 128, HQ), 256, GSMEM>>>(
        qh, ql, kh, kl, sc, HD, DMODEL, DKV, S_LEN,
        /*strA=*/HD, /*strB=*/HD, /*strC=*/(long long)S_LEN * S_LEN,
        /*bdivB=*/4, scale);

    // 5) softmax -> bf16 hi/lo P
    softmax_split<<<(HQ * S_LEN) / 8, 256>>>();

    // 6) attn[h] = P_h Vt_{h/4}^T (fp32 out)
    tcg_nt<<<dim3(HD / 128, S_LEN / 128, HQ), 256, GSMEM>>>(
        ph, pl, vth, vtl, attn, S_LEN, S_LEN, S_LEN, DMODEL,
        /*strA=*/(long long)S_LEN * S_LEN, /*strB=*/(long long)HD * S_LEN,
        /*strC=*/HD, /*bdivB=*/4, 1.0f);

    // 7) split attn, final projection
    SPLIT(attn, ah, al, (long long)S_LEN * DMODEL);
    tcg_nt<<<dim3(DMODEL / 128, S_LEN / 128, 1), 256, GSMEM>>>(
        ah, al, woh, wol, out, DMODEL, DMODEL, DMODEL, DMODEL, 0, 0, 0, 1, 1.0f);
}

// round 8
// speedup vs baseline: 1.0139x; 1.0139x over previous
#include <cuda_runtime.h>
#include <cuda_bf16.h>
#include <cstdint>
#include <math.h>

// Problem constants
#define S_LEN  2048
#define DMODEL 4096
#define HQ     32
#define HKV    8
#define HD     128
#define DKV    (HKV * HD)   // 1024

// ---------------------------------------------------------------------------
// Scratch (device globals)
// ---------------------------------------------------------------------------
__device__ float g_q[(size_t)S_LEN * DMODEL];       // fp32 Q projection
__device__ float g_k[(size_t)S_LEN * DKV];          // fp32 K projection
__device__ float g_v[(size_t)S_LEN * DKV];          // fp32 V projection

// bf16 hi/lo split operands
__device__ __nv_bfloat16 g_xh[(size_t)S_LEN * DMODEL],  g_xl[(size_t)S_LEN * DMODEL];
__device__ __nv_bfloat16 g_wqh[(size_t)DMODEL * DMODEL], g_wql[(size_t)DMODEL * DMODEL];
__device__ __nv_bfloat16 g_wkh[(size_t)DKV * DMODEL],    g_wkl[(size_t)DKV * DMODEL];
__device__ __nv_bfloat16 g_wvh[(size_t)DKV * DMODEL],    g_wvl[(size_t)DKV * DMODEL];
__device__ __nv_bfloat16 g_woh[(size_t)DMODEL * DMODEL], g_wol[(size_t)DMODEL * DMODEL];
__device__ __nv_bfloat16 g_qh[(size_t)S_LEN * DMODEL],   g_ql[(size_t)S_LEN * DMODEL];
__device__ __nv_bfloat16 g_kh[(size_t)S_LEN * DKV],      g_kl[(size_t)S_LEN * DKV];
__device__ __nv_bfloat16 g_vth[(size_t)DKV * S_LEN],     g_vtl[(size_t)DKV * S_LEN];
__device__ __nv_bfloat16 g_ah[(size_t)S_LEN * DMODEL],   g_al[(size_t)S_LEN * DMODEL];

// ---------------------------------------------------------------------------
// PTX helpers
// ---------------------------------------------------------------------------
__device__ __forceinline__ uint32_t smem_u32(const void* p) {
    uint32_t a;
    asm("{ .reg .u64 t; cvta.to.shared.u64 t, %1; cvt.u32.u64 %0, t; }"
        : "=r"(a) : "l"(p));
    return a;
}
__device__ __forceinline__ void ldsm_x4(uint32_t r[4], uint32_t addr) {
    asm volatile("ldmatrix.sync.aligned.m8n8.x4.shared.b16 {%0,%1,%2,%3}, [%4];"
        : "=r"(r[0]), "=r"(r[1]), "=r"(r[2]), "=r"(r[3]) : "r"(addr));
}
__device__ __forceinline__ void ldsm_x2(uint32_t r[2], uint32_t addr) {
    asm volatile("ldmatrix.sync.aligned.m8n8.x2.shared.b16 {%0,%1}, [%2];"
        : "=r"(r[0]), "=r"(r[1]) : "r"(addr));
}
__device__ __forceinline__ void mma_bf16(float d[4], const uint32_t a[4],
                                         const uint32_t b[2]) {
    asm volatile(
        "mma.sync.aligned.m16n8k16.row.col.f32.bf16.bf16.f32 "
        "{%0,%1,%2,%3}, {%4,%5,%6,%7}, {%8,%9}, {%0,%1,%2,%3};"
        : "+f"(d[0]), "+f"(d[1]), "+f"(d[2]), "+f"(d[3])
        : "r"(a[0]), "r"(a[1]), "r"(a[2]), "r"(a[3]), "r"(b[0]), "r"(b[1]));
}
#define CP_ASYNC16(sm_addr, gptr) \
    asm volatile("cp.async.cg.shared.global [%0], [%1], 16;" \
                 :: "r"(sm_addr), "l"(gptr) : "memory")
#define CP_COMMIT() asm volatile("cp.async.commit_group;" ::: "memory")
#define CP_WAIT0()  asm volatile("cp.async.wait_group 0;" ::: "memory")

__device__ __forceinline__ void split2(float x, __nv_bfloat16& h, __nv_bfloat16& l) {
    h = __float2bfloat16(x);
    l = __float2bfloat16(x - __bfloat162float(h));
}
__device__ __forceinline__ uint32_t packpair(__nv_bfloat16 a, __nv_bfloat16 b) {
    __nv_bfloat162 t = __halves2bfloat162(a, b);   // a -> low half
    return *reinterpret_cast<uint32_t*>(&t);
}

// ---------------------------------------------------------------------------
// bf16-split tensor-core GEMM NT with cp.async double-buffer (proven R6 core)
// ---------------------------------------------------------------------------
#define TILE_B (128 * 80)
#define STAGE_B (4 * TILE_B)
#define GSMEM  (2 * STAGE_B)

__global__ __launch_bounds__(256) void tcg_nt(
    const __nv_bfloat16* __restrict__ Ah, const __nv_bfloat16* __restrict__ Al,
    const __nv_bfloat16* __restrict__ Bh, const __nv_bfloat16* __restrict__ Bl,
    float* __restrict__ C, int K, int lda, int ldb, int ldc, float alpha)
{
    extern __shared__ char smem[];
    const uint32_t sbase = smem_u32(smem);

    const int row0 = blockIdx.y * 128;
    const int col0 = blockIdx.x * 128;
    const int tid  = threadIdx.x;
    const int lane = tid & 31;
    const int w    = tid >> 5;
    const int wm   = (w & 1) * 64;
    const int wn   = (w >> 1) * 32;

    const int pr  = (tid << 1) >> 2;
    const int pr1 = ((tid << 1) + 1) >> 2;
    const int pc  = ((tid << 1) & 3) * 8;
    const int pc1 = (((tid << 1) + 1) & 3) * 8;

    float acc[4][4][4];
#pragma unroll
    for (int i = 0; i < 4; i++)
#pragma unroll
        for (int j = 0; j < 4; j++)
#pragma unroll
            for (int e = 0; e < 4; e++) acc[i][j][e] = 0.f;

    const int KT = K / 32;

#define PREFETCH(kt, stage) do {                                               \
    const int k0 = (kt) * 32;                                                  \
    const uint32_t ss = sbase + (stage) * STAGE_B;                             \
    uint32_t o0 = (uint32_t)(pr  * 80 + pc  * 2);                              \
    uint32_t o1 = (uint32_t)(pr1 * 80 + pc1 * 2);                              \
    CP_ASYNC16(ss + o0,              Ah + (long long)(row0 + pr ) * lda + k0 + pc ); \
    CP_ASYNC16(ss + o1,              Ah + (long long)(row0 + pr1) * lda + k0 + pc1); \
    CP_ASYNC16(ss + TILE_B + o0,     Al + (long long)(row0 + pr ) * lda + k0 + pc ); \
    CP_ASYNC16(ss + TILE_B + o1,     Al + (long long)(row0 + pr1) * lda + k0 + pc1); \
    CP_ASYNC16(ss + 2 * TILE_B + o0, Bh + (long long)(col0 + pr ) * ldb + k0 + pc ); \
    CP_ASYNC16(ss + 2 * TILE_B + o1, Bh + (long long)(col0 + pr1) * ldb + k0 + pc1); \
    CP_ASYNC16(ss + 3 * TILE_B + o0, Bl + (long long)(col0 + pr ) * ldb + k0 + pc ); \
    CP_ASYNC16(ss + 3 * TILE_B + o1, Bl + (long long)(col0 + pr1) * ldb + k0 + pc1); \
} while (0)

    PREFETCH(0, 0);
    CP_COMMIT();

    for (int kt = 0; kt < KT; kt++) {
        CP_WAIT0();
        __syncthreads();
        if (kt + 1 < KT) {
            PREFETCH(kt + 1, (kt + 1) & 1);
            CP_COMMIT();
        }
        const uint32_t ss = sbase + (kt & 1) * STAGE_B;
        const uint32_t ah0 = ss, al0 = ss + TILE_B;
        const uint32_t bh0 = ss + 2 * TILE_B, bl0 = ss + 3 * TILE_B;

#pragma unroll
        for (int kc = 0; kc < 2; kc++) {
            const int kb = kc * 16;
            uint32_t afh[4][4], afl[4][4], bfh[4][2], bfl[4][2];
            {
                int rr = lane & 15;
                int cc = kb + ((lane >> 4) << 3);
#pragma unroll
                for (int mi = 0; mi < 4; mi++) {
                    uint32_t off = (uint32_t)((wm + mi * 16 + rr) * 80 + cc * 2);
                    ldsm_x4(afh[mi], ah0 + off);
                    ldsm_x4(afl[mi], al0 + off);
                }
            }
            {
                int rr = lane & 7;
                int cc = kb + (((lane >> 3) & 1) << 3);
#pragma unroll
                for (int nj = 0; nj < 4; nj++) {
                    uint32_t off = (uint32_t)((wn + nj * 8 + rr) * 80 + cc * 2);
                    ldsm_x2(bfh[nj], bh0 + off);
                    ldsm_x2(bfl[nj], bl0 + off);
                }
            }
#pragma unroll
            for (int mi = 0; mi < 4; mi++)
#pragma unroll
                for (int nj = 0; nj < 4; nj++) {
                    mma_bf16(acc[mi][nj], afh[mi], bfh[nj]);
                    mma_bf16(acc[mi][nj], afh[mi], bfl[nj]);
                    mma_bf16(acc[mi][nj], afl[mi], bfh[nj]);
                }
        }
        __syncthreads();
    }
#undef PREFETCH

#pragma unroll
    for (int mi = 0; mi < 4; mi++)
#pragma unroll
        for (int nj = 0; nj < 4; nj++) {
            int r = row0 + wm + mi * 16 + (lane >> 2);
            int c = col0 + wn + nj * 8 + (lane & 3) * 2;
            float* p0 = C + (long long)r * ldc + c;
            p0[0] = acc[mi][nj][0] * alpha;
            p0[1] = acc[mi][nj][1] * alpha;
            float* p1 = C + (long long)(r + 8) * ldc + c;
            p1[0] = acc[mi][nj][2] * alpha;
            p1[1] = acc[mi][nj][3] * alpha;
        }
}

// ---------------------------------------------------------------------------
// Fused flash attention: QK^T + online softmax + PV, bf16 hi/lo in/out.
// CTA = 64 q-rows x 1 head, 128 threads (4 warps, warp = 16 rows).
// K-tiles of 64. Output written as bf16 hi/lo to g_ah/g_al.
// Q is pre-scaled by 1/sqrt(128) in rope_split.
// ---------------------------------------------------------------------------
#define FA_QH 0
#define FA_QL 17408
#define FA_KH 34816
#define FA_KL 52224
#define FA_VH 69632
#define FA_VL 88064
#define FA_SMEM 106496
// pitches (bytes): Q/K rows 272 (128 bf16 + pad), Vt rows 144 (64 bf16 + pad)

__global__ __launch_bounds__(128) void flash_attn() {
    extern __shared__ char smem[];
    const uint32_t sb = smem_u32(smem);

    const int qb   = blockIdx.x;         // q block (64 rows)
    const int h    = blockIdx.y;         // head
    const int kvh  = h >> 2;
    const int q0   = qb * 64;
    const int tid  = threadIdx.x;
    const int lane = tid & 31;
    const int w    = tid >> 5;

    const __nv_bfloat16* Qh = g_qh;  const __nv_bfloat16* Ql = g_ql;
    const __nv_bfloat16* Kh = g_kh;  const __nv_bfloat16* Kl = g_kl;
    const __nv_bfloat16* Vh = g_vth; const __nv_bfloat16* Vl = g_vtl;

    // ---- load Q tile (64 x 128 hi/lo) once ----
#pragma unroll
    for (int i = 0; i < 8; i++) {
        int idx = tid + 128 * i;           // 0..1023
        int r = idx >> 4;                  // 0..63
        int c = (idx & 15) * 8;            // bf16 col
        uint32_t so = (uint32_t)(r * 272 + (idx & 15) * 16);
        CP_ASYNC16(sb + FA_QH + so, Qh + (long long)(q0 + r) * DMODEL + h * HD + c);
        CP_ASYNC16(sb + FA_QL + so, Ql + (long long)(q0 + r) * DMODEL + h * HD + c);
    }
    CP_COMMIT();

    float out[16][4];
#pragma unroll
    for (int i = 0; i < 16; i++)
#pragma unroll
        for (int e = 0; e < 4; e++) out[i][e] = 0.f;
    float m0 = -1e30f, m1 = -1e30f, l0 = 0.f, l1 = 0.f;

    for (int kt = 0; kt < S_LEN / 64; kt++) {
        const int s0 = kt * 64;
        // ---- load K tile (64 x 128) and Vt tile (128 x 64), hi/lo ----
        __syncthreads();   // previous iteration's reads done
#pragma unroll
        for (int i = 0; i < 8; i++) {
            int idx = tid + 128 * i;
            int r = idx >> 4;
            int c = (idx & 15) * 8;
            uint32_t so = (uint32_t)(r * 272 + (idx & 15) * 16);
            CP_ASYNC16(sb + FA_KH + so, Kh + (long long)(s0 + r) * DKV + kvh * HD + c);
            CP_ASYNC16(sb + FA_KL + so, Kl + (long long)(s0 + r) * DKV + kvh * HD + c);
        }
#pragma unroll
        for (int i = 0; i < 8; i++) {
            int idx = tid + 128 * i;
            int r = idx >> 3;                // 0..127 (d)
            int c = (idx & 7) * 8;           // s col
            uint32_t so = (uint32_t)(r * 144 + (idx & 7) * 16);
            CP_ASYNC16(sb + FA_VH + so, Vh + (long long)(kvh * HD + r) * S_LEN + s0 + c);
            CP_ASYNC16(sb + FA_VL + so, Vl + (long long)(kvh * HD + r) * S_LEN + s0 + c);
        }
        CP_COMMIT();
        CP_WAIT0();
        __syncthreads();

        // ---- QK^T: s_acc[nj][4], nj over 64 k-cols ----
        float s_acc[8][4];
#pragma unroll
        for (int nj = 0; nj < 8; nj++)
#pragma unroll
            for (int e = 0; e < 4; e++) s_acc[nj][e] = 0.f;

#pragma unroll
        for (int kc = 0; kc < 8; kc++) {
            uint32_t qa_h[4], qa_l[4];
            {
                int rr = lane & 15;
                int cc = kc * 16 + ((lane >> 4) << 3);
                uint32_t off = (uint32_t)((w * 16 + rr) * 272 + cc * 2);
                ldsm_x4(qa_h, sb + FA_QH + off);
                ldsm_x4(qa_l, sb + FA_QL + off);
            }
            int rr = lane & 7;
            int cc = kc * 16 + (((lane >> 3) & 1) << 3);
#pragma unroll
            for (int nj = 0; nj < 8; nj++) {
                uint32_t bh[2], bl[2];
                uint32_t off = (uint32_t)((nj * 8 + rr) * 272 + cc * 2);
                ldsm_x2(bh, sb + FA_KH + off);
                ldsm_x2(bl, sb + FA_KL + off);
                mma_bf16(s_acc[nj], qa_h, bh);
                mma_bf16(s_acc[nj], qa_h, bl);
                mma_bf16(s_acc[nj], qa_l, bh);
            }
        }

        // ---- online softmax (rows warp-local; slot0 = lane>>2, slot1 = +8) ----
        float mt0 = -1e30f, mt1 = -1e30f;
#pragma unroll
        for (int nj = 0; nj < 8; nj++) {
            mt0 = fmaxf(mt0, fmaxf(s_acc[nj][0], s_acc[nj][1]));
            mt1 = fmaxf(mt1, fmaxf(s_acc[nj][2], s_acc[nj][3]));
        }
        mt0 = fmaxf(mt0, __shfl_xor_sync(0xffffffffu, mt0, 1));
        mt0 = fmaxf(mt0, __shfl_xor_sync(0xffffffffu, mt0, 2));
        mt1 = fmaxf(mt1, __shfl_xor_sync(0xffffffffu, mt1, 1));
        mt1 = fmaxf(mt1, __shfl_xor_sync(0xffffffffu, mt1, 2));

        float mn0 = fmaxf(m0, mt0), mn1 = fmaxf(m1, mt1);
        float a0 = __expf(m0 - mn0), a1 = __expf(m1 - mn1);
        float sum0 = 0.f, sum1 = 0.f;
#pragma unroll
        for (int nj = 0; nj < 8; nj++) {
            s_acc[nj][0] = __expf(s_acc[nj][0] - mn0);
            s_acc[nj][1] = __expf(s_acc[nj][1] - mn0);
            s_acc[nj][2] = __expf(s_acc[nj][2] - mn1);
            s_acc[nj][3] = __expf(s_acc[nj][3] - mn1);
            sum0 += s_acc[nj][0] + s_acc[nj][1];
            sum1 += s_acc[nj][2] + s_acc[nj][3];
        }
        sum0 += __shfl_xor_sync(0xffffffffu, sum0, 1);
        sum0 += __shfl_xor_sync(0xffffffffu, sum0, 2);
        sum1 += __shfl_xor_sync(0xffffffffu, sum1, 1);
        sum1 += __shfl_xor_sync(0xffffffffu, sum1, 2);
        l0 = l0 * a0 + sum0;  m0 = mn0;
        l1 = l1 * a1 + sum1;  m1 = mn1;
#pragma unroll
        for (int i = 0; i < 16; i++) {
            out[i][0] *= a0; out[i][1] *= a0;
            out[i][2] *= a1; out[i][3] *= a1;
        }

        // ---- PV: P (regs, hi/lo) x Vt tiles ----
#pragma unroll
        for (int kc = 0; kc < 4; kc++) {
            uint32_t pah[4], pal[4];
            {
                __nv_bfloat16 h0, h1, lo0, lo1;
                split2(s_acc[2 * kc][0], h0, lo0); split2(s_acc[2 * kc][1], h1, lo1);
                pah[0] = packpair(h0, h1); pal[0] = packpair(lo0, lo1);
                split2(s_acc[2 * kc][2], h0, lo0); split2(s_acc[2 * kc][3], h1, lo1);
                pah[1] = packpair(h0, h1); pal[1] = packpair(lo0, lo1);
                split2(s_acc[2 * kc + 1][0], h0, lo0); split2(s_acc[2 * kc + 1][1], h1, lo1);
                pah[2] = packpair(h0, h1); pal[2] = packpair(lo0, lo1);
                split2(s_acc[2 * kc + 1][2], h0, lo0); split2(s_acc[2 * kc + 1][3], h1, lo1);
                pah[3] = packpair(h0, h1); pal[3] = packpair(lo0, lo1);
            }
            int rr = lane & 7;
            int cc = kc * 16 + (((lane >> 3) & 1) << 3);
#pragma unroll
            for (int nd = 0; nd < 16; nd++) {
                uint32_t vh[2], vl[2];
                uint32_t off = (uint32_t)((nd * 8 + rr) * 144 + cc * 2);
                ldsm_x2(vh, sb + FA_VH + off);
                ldsm_x2(vl, sb + FA_VL + off);
                mma_bf16(out[nd], pah, vh);
                mma_bf16(out[nd], pah, vl);
                mma_bf16(out[nd], pal, vh);
            }
        }
    }

    // ---- epilogue: normalize, split to bf16 hi/lo, store ----
    float inv0 = 1.0f / l0, inv1 = 1.0f / l1;
    int row0 = q0 + w * 16 + (lane >> 2);
    int row1 = row0 + 8;
#pragma unroll
    for (int nd = 0; nd < 16; nd++) {
        int col = h * HD + nd * 8 + (lane & 3) * 2;
        __nv_bfloat16 h0, h1, lo0, lo1;
        split2(out[nd][0] * inv0, h0, lo0);
        split2(out[nd][1] * inv0, h1, lo1);
        *(uint32_t*)(g_ah + (size_t)row0 * DMODEL + col) = packpair(h0, h1);
        *(uint32_t*)(g_al + (size_t)row0 * DMODEL + col) = packpair(lo0, lo1);
        split2(out[nd][2] * inv1, h0, lo0);
        split2(out[nd][3] * inv1, h1, lo1);
        *(uint32_t*)(g_ah + (size_t)row1 * DMODEL + col) = packpair(h0, h1);
        *(uint32_t*)(g_al + (size_t)row1 * DMODEL + col) = packpair(lo0, lo1);
    }
}

// ---------------------------------------------------------------------------
// Elementwise split: fp32 -> bf16 hi/lo
// ---------------------------------------------------------------------------
__global__ void split_f32(const float* __restrict__ in,
                          __nv_bfloat16* __restrict__ hi,
                          __nv_bfloat16* __restrict__ lo, long long n)
{
    long long i4 = ((long long)blockIdx.x * blockDim.x + threadIdx.x) * 4;
    if (i4 >= n) return;
    float4 v = *(const float4*)(in + i4);
    __nv_bfloat16 h0, h1, h2, h3, l0, l1, l2, l3;
    split2(v.x, h0, l0); split2(v.y, h1, l1);
    split2(v.z, h2, l2); split2(v.w, h3, l3);
    *(uint2*)(hi + i4) = make_uint2(packpair(h0, h1), packpair(h2, h3));
    *(uint2*)(lo + i4) = make_uint2(packpair(l0, l1), packpair(l2, l3));
}

// ---------------------------------------------------------------------------
// RoPE: fp32 in, bf16 hi/lo out. Q additionally scaled by 1/sqrt(128).
// ---------------------------------------------------------------------------
__global__ void rope_split() {
    long long idx = (long long)blockIdx.x * blockDim.x + threadIdx.x;
    const long long QP = (long long)S_LEN * HQ * 64;
    const long long KP = (long long)S_LEN * HKV * 64;
    if (idx >= QP + KP) return;

    const float* src; __nv_bfloat16 *dh, *dl;
    int s, h, i, stride; float postscale;
    if (idx < QP) {
        s = (int)(idx / (HQ * 64));
        int rem = (int)(idx % (HQ * 64));
        h = rem / 64; i = rem % 64;
        src = g_q; dh = g_qh; dl = g_ql; stride = DMODEL;
        postscale = 0.08838834764831845f;   // 1/sqrt(128)
    } else {
        long long t = idx - QP;
        s = (int)(t / (HKV * 64));
        int rem = (int)(t % (HKV * 64));
        h = rem / 64; i = rem % 64;
        src = g_k; dh = g_kh; dl = g_kl; stride = DKV;
        postscale = 1.0f;
    }

    float invf = (float)(1.0 / pow(10000.0, (double)i / 64.0));
    float ang = (float)s * invf;
    double sd, cd;
    sincos((double)ang, &sd, &cd);
    float c = (float)cd, sn = (float)sd;

    size_t off = (size_t)s * (size_t)stride + (size_t)h * HD + 2 * (size_t)i;
    float x1 = src[off], x2 = src[off + 1];
    float o1 = (x1 * c - x2 * sn) * postscale;
    float o2 = (x1 * sn + x2 * c) * postscale;
    __nv_bfloat16 h1, h2, l1, l2;
    split2(o1, h1, l1); split2(o2, h2, l2);
    *(uint32_t*)(dh + off) = packpair(h1, h2);
    *(uint32_t*)(dl + off) = packpair(l1, l2);
}

// ---------------------------------------------------------------------------
// Transpose V [s][d] -> Vt [d][s], bf16 hi/lo
// ---------------------------------------------------------------------------
__global__ void transpose_v_split() {
    __shared__ float t[32][33];
    int d0 = blockIdx.x * 32;
    int s0 = blockIdx.y * 32;
    for (int i = threadIdx.y; i < 32; i += 8)
        t[i][threadIdx.x] = g_v[(size_t)(s0 + i) * DKV + d0 + threadIdx.x];
    __syncthreads();
    for (int i = threadIdx.y; i < 32; i += 8) {
        float v = t[threadIdx.x][i];
        __nv_bfloat16 h, l;
        split2(v, h, l);
        size_t o = (size_t)(d0 + i) * S_LEN + s0 + threadIdx.x;
        g_vth[o] = h;
        g_vtl[o] = l;
    }
}

// ---------------------------------------------------------------------------
// Launch
// ---------------------------------------------------------------------------
extern "C" void kernel_launch(void* const* d_in, const int* in_sizes, int n_in,
                              void* d_out, int out_size)
{
    const float* x  = (const float*)d_in[0];
    const float* wq = (const float*)d_in[1];
    const float* wk = (const float*)d_in[2];
    const float* wv = (const float*)d_in[3];
    const float* wo = (const float*)d_in[4];
    float* out = (float*)d_out;

    float *q, *k, *v;
    cudaGetSymbolAddress((void**)&q, g_q);
    cudaGetSymbolAddress((void**)&k, g_k);
    cudaGetSymbolAddress((void**)&v, g_v);

    __nv_bfloat16 *xh, *xl, *wqh, *wql, *wkh, *wkl, *wvh, *wvl, *woh, *wol, *ah, *al;
    cudaGetSymbolAddress((void**)&xh,  g_xh);  cudaGetSymbolAddress((void**)&xl,  g_xl);
    cudaGetSymbolAddress((void**)&wqh, g_wqh); cudaGetSymbolAddress((void**)&wql, g_wql);
    cudaGetSymbolAddress((void**)&wkh, g_wkh); cudaGetSymbolAddress((void**)&wkl, g_wkl);
    cudaGetSymbolAddress((void**)&wvh, g_wvh); cudaGetSymbolAddress((void**)&wvl, g_wvl);
    cudaGetSymbolAddress((void**)&woh, g_woh); cudaGetSymbolAddress((void**)&wol, g_wol);
    cudaGetSymbolAddress((void**)&ah,  g_ah);  cudaGetSymbolAddress((void**)&al,  g_al);

    cudaFuncSetAttribute(tcg_nt,
        cudaFuncAttributeMaxDynamicSharedMemorySize, GSMEM);
    cudaFuncSetAttribute(flash_attn,
        cudaFuncAttributeMaxDynamicSharedMemorySize, FA_SMEM);

#define SPLIT(src, h, l, n) \
    split_f32<<<(int)(((n) / 4 + 255) / 256), 256>>>(src, h, l, (long long)(n))

    // 0) split inputs
    SPLIT(x,  xh,  xl,  (long long)S_LEN * DMODEL);
    SPLIT(wq, wqh, wql, (long long)DMODEL * DMODEL);
    SPLIT(wk, wkh, wkl, (long long)DKV * DMODEL);
    SPLIT(wv, wvh, wvl, (long long)DKV * DMODEL);
    SPLIT(wo, woh, wol, (long long)DMODEL * DMODEL);

    // 1) Projections (fp32 out)
    tcg_nt<<<dim3(DMODEL / 128, S_LEN / 128), 256, GSMEM>>>(
        xh, xl, wqh, wql, q, DMODEL, DMODEL, DMODEL, DMODEL, 1.0f);
    tcg_nt<<<dim3(DKV / 128, S_LEN / 128), 256, GSMEM>>>(
        xh, xl, wkh, wkl, k, DMODEL, DMODEL, DMODEL, DKV, 1.0f);
    tcg_nt<<<dim3(DKV / 128, S_LEN / 128), 256, GSMEM>>>(
        xh, xl, wvh, wvl, v, DMODEL, DMODEL, DMODEL, DKV, 1.0f);

    // 2) RoPE -> bf16 hi/lo Q (pre-scaled), K
    {
        long long total = (long long)S_LEN * HQ * 64 + (long long)S_LEN * HKV * 64;
        rope_split<<<(int)((total + 255) / 256), 256>>>();
    }

    // 3) V transpose -> bf16 hi/lo Vt
    transpose_v_split<<<dim3(DKV / 32, S_LEN / 32), dim3(32, 8)>>>();

    // 4) Fused attention -> g_ah/g_al (bf16 hi/lo)
    flash_attn<<<dim3(S_LEN / 64, HQ), 128, FA_SMEM>>>();

    // 5) out = attn * wo^T
    tcg_nt<<<dim3(DMODEL / 128, S_LEN / 128), 256, GSMEM>>>(
        ah, al, woh, wol, out, DMODEL, DMODEL, DMODEL, DMODEL, 1.0f);
}

// round 9
// speedup vs baseline: 1.0733x; 1.0586x over previous
#include <cuda_runtime.h>
#include <cuda_bf16.h>
#include <cstdint>
#include <math.h>

// Problem constants
#define S_LEN  2048
#define DMODEL 4096
#define HQ     32
#define HKV    8
#define HD     128
#define DKV    (HKV * HD)   // 1024

// ---------------------------------------------------------------------------
// Scratch (device globals)
// ---------------------------------------------------------------------------
__device__ float g_q[(size_t)S_LEN * DMODEL];
__device__ float g_k[(size_t)S_LEN * DKV];
__device__ float g_v[(size_t)S_LEN * DKV];

__device__ __nv_bfloat16 g_xh[(size_t)S_LEN * DMODEL],  g_xl[(size_t)S_LEN * DMODEL];
__device__ __nv_bfloat16 g_wqh[(size_t)DMODEL * DMODEL], g_wql[(size_t)DMODEL * DMODEL];
__device__ __nv_bfloat16 g_wkh[(size_t)DKV * DMODEL],    g_wkl[(size_t)DKV * DMODEL];
__device__ __nv_bfloat16 g_wvh[(size_t)DKV * DMODEL],    g_wvl[(size_t)DKV * DMODEL];
__device__ __nv_bfloat16 g_woh[(size_t)DMODEL * DMODEL], g_wol[(size_t)DMODEL * DMODEL];
__device__ __nv_bfloat16 g_qh[(size_t)S_LEN * DMODEL],   g_ql[(size_t)S_LEN * DMODEL];
__device__ __nv_bfloat16 g_kh[(size_t)S_LEN * DKV],      g_kl[(size_t)S_LEN * DKV];
__device__ __nv_bfloat16 g_vth[(size_t)DKV * S_LEN],     g_vtl[(size_t)DKV * S_LEN];
__device__ __nv_bfloat16 g_ah[(size_t)S_LEN * DMODEL],   g_al[(size_t)S_LEN * DMODEL];

// ---------------------------------------------------------------------------
// PTX helpers
// ---------------------------------------------------------------------------
__device__ __forceinline__ uint32_t smem_u32(const void* p) {
    uint32_t a;
    asm("{ .reg .u64 t; cvta.to.shared.u64 t, %1; cvt.u32.u64 %0, t; }"
        : "=r"(a) : "l"(p));
    return a;
}
__device__ __forceinline__ void ldsm_x4(uint32_t r[4], uint32_t addr) {
    asm volatile("ldmatrix.sync.aligned.m8n8.x4.shared.b16 {%0,%1,%2,%3}, [%4];"
        : "=r"(r[0]), "=r"(r[1]), "=r"(r[2]), "=r"(r[3]) : "r"(addr));
}
__device__ __forceinline__ void mma_bf16(float d[4], const uint32_t a[4],
                                         const uint32_t b[2]) {
    asm volatile(
        "mma.sync.aligned.m16n8k16.row.col.f32.bf16.bf16.f32 "
        "{%0,%1,%2,%3}, {%4,%5,%6,%7}, {%8,%9}, {%0,%1,%2,%3};"
        : "+f"(d[0]), "+f"(d[1]), "+f"(d[2]), "+f"(d[3])
        : "r"(a[0]), "r"(a[1]), "r"(a[2]), "r"(a[3]), "r"(b[0]), "r"(b[1]));
}
#define CP_ASYNC16(sm_addr, gptr) \
    asm volatile("cp.async.cg.shared.global [%0], [%1], 16;" \
                 :: "r"(sm_addr), "l"(gptr) : "memory")
#define CP_COMMIT() asm volatile("cp.async.commit_group;" ::: "memory")
#define CP_WAIT0()  asm volatile("cp.async.wait_group 0;" ::: "memory")

__device__ __forceinline__ void split2(float x, __nv_bfloat16& h, __nv_bfloat16& l) {
    h = __float2bfloat16(x);
    l = __float2bfloat16(x - __bfloat162float(h));
}
__device__ __forceinline__ uint32_t packpair(__nv_bfloat16 a, __nv_bfloat16 b) {
    __nv_bfloat162 t = __halves2bfloat162(a, b);
    return *reinterpret_cast<uint32_t*>(&t);
}

// ---------------------------------------------------------------------------
// Shared GEMM core: C[128 rows @row0, 128 cols @col0] = alpha*(Ah+Al)(Bh+Bl)^T
// 256 threads, K-step 32, cp.async double-buffer, ldsm_x4 for A and B.
// ---------------------------------------------------------------------------
#define TILE_B (128 * 80)
#define STAGE_B (4 * TILE_B)
#define GSMEM  (2 * STAGE_B)

__device__ __forceinline__ void gemm_core(
    const __nv_bfloat16* __restrict__ Ah, const __nv_bfloat16* __restrict__ Al,
    const __nv_bfloat16* __restrict__ Bh, const __nv_bfloat16* __restrict__ Bl,
    float* __restrict__ C, int K, int lda, int ldb, int ldc,
    int row0, int col0, float alpha, char* smem)
{
    const uint32_t sbase = smem_u32(smem);
    const int tid  = threadIdx.x;
    const int lane = tid & 31;
    const int w    = tid >> 5;
    const int wm   = (w & 1) * 64;
    const int wn   = (w >> 1) * 32;

    const int pr  = (tid << 1) >> 2;
    const int pr1 = ((tid << 1) + 1) >> 2;
    const int pc  = ((tid << 1) & 3) * 8;
    const int pc1 = (((tid << 1) + 1) & 3) * 8;

    float acc[4][4][4];
#pragma unroll
    for (int i = 0; i < 4; i++)
#pragma unroll
        for (int j = 0; j < 4; j++)
#pragma unroll
            for (int e = 0; e < 4; e++) acc[i][j][e] = 0.f;

    const int KT = K / 32;

#define PREFETCH(kt, stage) do {                                               \
    const int k0 = (kt) * 32;                                                  \
    const uint32_t ss = sbase + (stage) * STAGE_B;                             \
    uint32_t o0 = (uint32_t)(pr  * 80 + pc  * 2);                              \
    uint32_t o1 = (uint32_t)(pr1 * 80 + pc1 * 2);                              \
    CP_ASYNC16(ss + o0,              Ah + (long long)(row0 + pr ) * lda + k0 + pc ); \
    CP_ASYNC16(ss + o1,              Ah + (long long)(row0 + pr1) * lda + k0 + pc1); \
    CP_ASYNC16(ss + TILE_B + o0,     Al + (long long)(row0 + pr ) * lda + k0 + pc ); \
    CP_ASYNC16(ss + TILE_B + o1,     Al + (long long)(row0 + pr1) * lda + k0 + pc1); \
    CP_ASYNC16(ss + 2 * TILE_B + o0, Bh + (long long)(col0 + pr ) * ldb + k0 + pc ); \
    CP_ASYNC16(ss + 2 * TILE_B + o1, Bh + (long long)(col0 + pr1) * ldb + k0 + pc1); \
    CP_ASYNC16(ss + 3 * TILE_B + o0, Bl + (long long)(col0 + pr ) * ldb + k0 + pc ); \
    CP_ASYNC16(ss + 3 * TILE_B + o1, Bl + (long long)(col0 + pr1) * ldb + k0 + pc1); \
} while (0)

    PREFETCH(0, 0);
    CP_COMMIT();

    for (int kt = 0; kt < KT; kt++) {
        CP_WAIT0();
        __syncthreads();
        if (kt + 1 < KT) {
            PREFETCH(kt + 1, (kt + 1) & 1);
            CP_COMMIT();
        }
        const uint32_t ss = sbase + (kt & 1) * STAGE_B;
        const uint32_t ah0 = ss, al0 = ss + TILE_B;
        const uint32_t bh0 = ss + 2 * TILE_B, bl0 = ss + 3 * TILE_B;

#pragma unroll
        for (int kc = 0; kc < 2; kc++) {
            const int kb = kc * 16;
            uint32_t afh[4][4], afl[4][4];
            {
                int rr = lane & 15;
                int cc = kb + ((lane >> 4) << 3);
#pragma unroll
                for (int mi = 0; mi < 4; mi++) {
                    uint32_t off = (uint32_t)((wm + mi * 16 + rr) * 80 + cc * 2);
                    ldsm_x4(afh[mi], ah0 + off);
                    ldsm_x4(afl[mi], al0 + off);
                }
            }
            {
                int rr    = lane & 7;
                int cc    = kb + (((lane >> 3) & 1) << 3);
                int njoff = (lane >> 4) << 3;
#pragma unroll
                for (int njp = 0; njp < 2; njp++) {
                    uint32_t bh4[4], bl4[4];
                    uint32_t off = (uint32_t)((wn + njp * 16 + njoff + rr) * 80 + cc * 2);
                    ldsm_x4(bh4, bh0 + off);
                    ldsm_x4(bl4, bl0 + off);
#pragma unroll
                    for (int mi = 0; mi < 4; mi++) {
                        mma_bf16(acc[mi][2 * njp], afh[mi], bh4);
                        mma_bf16(acc[mi][2 * njp], afh[mi], bl4);
                        mma_bf16(acc[mi][2 * njp], afl[mi], bh4);
                        mma_bf16(acc[mi][2 * njp + 1], afh[mi], bh4 + 2);
                        mma_bf16(acc[mi][2 * njp + 1], afh[mi], bl4 + 2);
                        mma_bf16(acc[mi][2 * njp + 1], afl[mi], bh4 + 2);
                    }
                }
            }
        }
        __syncthreads();
    }
#undef PREFETCH

#pragma unroll
    for (int mi = 0; mi < 4; mi++)
#pragma unroll
        for (int nj = 0; nj < 4; nj++) {
            int r = row0 + wm + mi * 16 + (lane >> 2);
            int c = col0 + wn + nj * 8 + (lane & 3) * 2;
            float* p0 = C + (long long)r * ldc + c;
            p0[0] = acc[mi][nj][0] * alpha;
            p0[1] = acc[mi][nj][1] * alpha;
            float* p1 = C + (long long)(r + 8) * ldc + c;
            p1[0] = acc[mi][nj][2] * alpha;
            p1[1] = acc[mi][nj][3] * alpha;
        }
}

// Merged Q/K/V projection: grid (48, 16). x-blocks 0-31 -> Q, 32-39 -> K, 40-47 -> V.
__global__ __launch_bounds__(256) void tcg_qkv() {
    extern __shared__ char smem[];
    const int cb = blockIdx.x;
    const __nv_bfloat16 *Bh, *Bl; float* C; int ldc, col0;
    if (cb < 32)      { Bh = g_wqh; Bl = g_wql; C = g_q; ldc = DMODEL; col0 = cb * 128; }
    else if (cb < 40) { Bh = g_wkh; Bl = g_wkl; C = g_k; ldc = DKV;    col0 = (cb - 32) * 128; }
    else              { Bh = g_wvh; Bl = g_wvl; C = g_v; ldc = DKV;    col0 = (cb - 40) * 128; }
    gemm_core(g_xh, g_xl, Bh, Bl, C, DMODEL, DMODEL, DMODEL, ldc,
              blockIdx.y * 128, col0, 1.0f, smem);
}

// Generic NT GEMM (used for wo)
__global__ __launch_bounds__(256) void tcg_nt(
    const __nv_bfloat16* __restrict__ Ah, const __nv_bfloat16* __restrict__ Al,
    const __nv_bfloat16* __restrict__ Bh, const __nv_bfloat16* __restrict__ Bl,
    float* __restrict__ C, int K, int lda, int ldb, int ldc, float alpha)
{
    extern __shared__ char smem[];
    gemm_core(Ah, Al, Bh, Bl, C, K, lda, ldb, ldc,
              blockIdx.y * 128, blockIdx.x * 128, alpha, smem);
}

// ---------------------------------------------------------------------------
// Fused flash attention (hi/lo bf16 in/out), ldsm_x4 B-operands.
// CTA = 64 q-rows x 1 head, 128 threads.
// ---------------------------------------------------------------------------
#define FA_QH 0
#define FA_QL 17408
#define FA_KH 34816
#define FA_KL 52224
#define FA_VH 69632
#define FA_VL 88064
#define FA_SMEM 106496

__global__ __launch_bounds__(128) void flash_attn() {
    extern __shared__ char smem[];
    const uint32_t sb = smem_u32(smem);

    const int qb   = blockIdx.x;
    const int h    = blockIdx.y;
    const int kvh  = h >> 2;
    const int q0   = qb * 64;
    const int tid  = threadIdx.x;
    const int lane = tid & 31;
    const int w    = tid >> 5;

    // Q tile (64 x 128 hi/lo), loaded once
#pragma unroll
    for (int i = 0; i < 8; i++) {
        int idx = tid + 128 * i;
        int r = idx >> 4;
        int c = (idx & 15) * 8;
        uint32_t so = (uint32_t)(r * 272 + (idx & 15) * 16);
        CP_ASYNC16(sb + FA_QH + so, g_qh + (long long)(q0 + r) * DMODEL + h * HD + c);
        CP_ASYNC16(sb + FA_QL + so, g_ql + (long long)(q0 + r) * DMODEL + h * HD + c);
    }
    CP_COMMIT();

    float out[16][4];
#pragma unroll
    for (int i = 0; i < 16; i++)
#pragma unroll
        for (int e = 0; e < 4; e++) out[i][e] = 0.f;
    float m0 = -1e30f, m1 = -1e30f, l0 = 0.f, l1 = 0.f;

    for (int kt = 0; kt < S_LEN / 64; kt++) {
        const int s0 = kt * 64;
        __syncthreads();
#pragma unroll
        for (int i = 0; i < 8; i++) {
            int idx = tid + 128 * i;
            int r = idx >> 4;
            int c = (idx & 15) * 8;
            uint32_t so = (uint32_t)(r * 272 + (idx & 15) * 16);
            CP_ASYNC16(sb + FA_KH + so, g_kh + (long long)(s0 + r) * DKV + kvh * HD + c);
            CP_ASYNC16(sb + FA_KL + so, g_kl + (long long)(s0 + r) * DKV + kvh * HD + c);
        }
#pragma unroll
        for (int i = 0; i < 8; i++) {
            int idx = tid + 128 * i;
            int r = idx >> 3;
            int c = (idx & 7) * 8;
            uint32_t so = (uint32_t)(r * 144 + (idx & 7) * 16);
            CP_ASYNC16(sb + FA_VH + so, g_vth + (long long)(kvh * HD + r) * S_LEN + s0 + c);
            CP_ASYNC16(sb + FA_VL + so, g_vtl + (long long)(kvh * HD + r) * S_LEN + s0 + c);
        }
        CP_COMMIT();
        CP_WAIT0();
        __syncthreads();

        // ---- QK^T ----
        float s_acc[8][4];
#pragma unroll
        for (int nj = 0; nj < 8; nj++)
#pragma unroll
            for (int e = 0; e < 4; e++) s_acc[nj][e] = 0.f;

#pragma unroll
        for (int kc = 0; kc < 8; kc++) {
            uint32_t qa_h[4], qa_l[4];
            {
                int rr = lane & 15;
                int cc = kc * 16 + ((lane >> 4) << 3);
                uint32_t off = (uint32_t)((w * 16 + rr) * 272 + cc * 2);
                ldsm_x4(qa_h, sb + FA_QH + off);
                ldsm_x4(qa_l, sb + FA_QL + off);
            }
            int rr    = lane & 7;
            int cc    = kc * 16 + (((lane >> 3) & 1) << 3);
            int njoff = (lane >> 4) << 3;
#pragma unroll
            for (int njp = 0; njp < 4; njp++) {
                uint32_t bh4[4], bl4[4];
                uint32_t off = (uint32_t)((njp * 16 + njoff + rr) * 272 + cc * 2);
                ldsm_x4(bh4, sb + FA_KH + off);
                ldsm_x4(bl4, sb + FA_KL + off);
                mma_bf16(s_acc[2 * njp], qa_h, bh4);
                mma_bf16(s_acc[2 * njp], qa_h, bl4);
                mma_bf16(s_acc[2 * njp], qa_l, bh4);
                mma_bf16(s_acc[2 * njp + 1], qa_h, bh4 + 2);
                mma_bf16(s_acc[2 * njp + 1], qa_h, bl4 + 2);
                mma_bf16(s_acc[2 * njp + 1], qa_l, bh4 + 2);
            }
        }

        // ---- online softmax ----
        float mt0 = -1e30f, mt1 = -1e30f;
#pragma unroll
        for (int nj = 0; nj < 8; nj++) {
            mt0 = fmaxf(mt0, fmaxf(s_acc[nj][0], s_acc[nj][1]));
            mt1 = fmaxf(mt1, fmaxf(s_acc[nj][2], s_acc[nj][3]));
        }
        mt0 = fmaxf(mt0, __shfl_xor_sync(0xffffffffu, mt0, 1));
        mt0 = fmaxf(mt0, __shfl_xor_sync(0xffffffffu, mt0, 2));
        mt1 = fmaxf(mt1, __shfl_xor_sync(0xffffffffu, mt1, 1));
        mt1 = fmaxf(mt1, __shfl_xor_sync(0xffffffffu, mt1, 2));

        float mn0 = fmaxf(m0, mt0), mn1 = fmaxf(m1, mt1);
        float a0 = __expf(m0 - mn0), a1 = __expf(m1 - mn1);
        float sum0 = 0.f, sum1 = 0.f;
#pragma unroll
        for (int nj = 0; nj < 8; nj++) {
            s_acc[nj][0] = __expf(s_acc[nj][0] - mn0);
            s_acc[nj][1] = __expf(s_acc[nj][1] - mn0);
            s_acc[nj][2] = __expf(s_acc[nj][2] - mn1);
            s_acc[nj][3] = __expf(s_acc[nj][3] - mn1);
            sum0 += s_acc[nj][0] + s_acc[nj][1];
            sum1 += s_acc[nj][2] + s_acc[nj][3];
        }
        sum0 += __shfl_xor_sync(0xffffffffu, sum0, 1);
        sum0 += __shfl_xor_sync(0xffffffffu, sum0, 2);
        sum1 += __shfl_xor_sync(0xffffffffu, sum1, 1);
        sum1 += __shfl_xor_sync(0xffffffffu, sum1, 2);
        l0 = l0 * a0 + sum0;  m0 = mn0;
        l1 = l1 * a1 + sum1;  m1 = mn1;
#pragma unroll
        for (int i = 0; i < 16; i++) {
            out[i][0] *= a0; out[i][1] *= a0;
            out[i][2] *= a1; out[i][3] *= a1;
        }

        // ---- PV ----
#pragma unroll
        for (int kc = 0; kc < 4; kc++) {
            uint32_t pah[4], pal[4];
            {
                __nv_bfloat16 h0, h1, lo0, lo1;
                split2(s_acc[2 * kc][0], h0, lo0); split2(s_acc[2 * kc][1], h1, lo1);
                pah[0] = packpair(h0, h1); pal[0] = packpair(lo0, lo1);
                split2(s_acc[2 * kc][2], h0, lo0); split2(s_acc[2 * kc][3], h1, lo1);
                pah[1] = packpair(h0, h1); pal[1] = packpair(lo0, lo1);
                split2(s_acc[2 * kc + 1][0], h0, lo0); split2(s_acc[2 * kc + 1][1], h1, lo1);
                pah[2] = packpair(h0, h1); pal[2] = packpair(lo0, lo1);
                split2(s_acc[2 * kc + 1][2], h0, lo0); split2(s_acc[2 * kc + 1][3], h1, lo1);
                pah[3] = packpair(h0, h1); pal[3] = packpair(lo0, lo1);
            }
            int rr    = lane & 7;
            int cc    = kc * 16 + (((lane >> 3) & 1) << 3);
            int ndoff = (lane >> 4) << 3;
#pragma unroll
            for (int ndp = 0; ndp < 8; ndp++) {
                uint32_t vh4[4], vl4[4];
                uint32_t off = (uint32_t)((ndp * 16 + ndoff + rr) * 144 + cc * 2);
                ldsm_x4(vh4, sb + FA_VH + off);
                ldsm_x4(vl4, sb + FA_VL + off);
                mma_bf16(out[2 * ndp], pah, vh4);
                mma_bf16(out[2 * ndp], pah, vl4);
                mma_bf16(out[2 * ndp], pal, vh4);
                mma_bf16(out[2 * ndp + 1], pah, vh4 + 2);
                mma_bf16(out[2 * ndp + 1], pah, vl4 + 2);
                mma_bf16(out[2 * ndp + 1], pal, vh4 + 2);
            }
        }
    }

    // ---- epilogue ----
    float inv0 = 1.0f / l0, inv1 = 1.0f / l1;
    int row0 = q0 + w * 16 + (lane >> 2);
    int row1 = row0 + 8;
#pragma unroll
    for (int nd = 0; nd < 16; nd++) {
        int col = h * HD + nd * 8 + (lane & 3) * 2;
        __nv_bfloat16 h0, h1, lo0, lo1;
        split2(out[nd][0] * inv0, h0, lo0);
        split2(out[nd][1] * inv0, h1, lo1);
        *(uint32_t*)(g_ah + (size_t)row0 * DMODEL + col) = packpair(h0, h1);
        *(uint32_t*)(g_al + (size_t)row0 * DMODEL + col) = packpair(lo0, lo1);
        split2(out[nd][2] * inv1, h0, lo0);
        split2(out[nd][3] * inv1, h1, lo1);
        *(uint32_t*)(g_ah + (size_t)row1 * DMODEL + col) = packpair(h0, h1);
        *(uint32_t*)(g_al + (size_t)row1 * DMODEL + col) = packpair(lo0, lo1);
    }
}

// ---------------------------------------------------------------------------
// Split: fp32 -> bf16 hi/lo, 4 independent float4s per thread (MLP=4)
// ---------------------------------------------------------------------------
__global__ void split_f32(const float* __restrict__ in,
                          __nv_bfloat16* __restrict__ hi,
                          __nv_bfloat16* __restrict__ lo, int n4)
{
    const int stride = gridDim.x * blockDim.x;
    const int i0 = blockIdx.x * blockDim.x + threadIdx.x;
    float4 v[4]; int idx[4]; int cnt = 0;
#pragma unroll
    for (int u = 0; u < 4; u++) {
        int j = i0 + u * stride;
        if (j < n4) { idx[cnt] = j; v[cnt] = ((const float4*)in)[j]; cnt++; }
    }
#pragma unroll 4
    for (int t = 0; t < cnt; t++) {
        __nv_bfloat16 h0, h1, h2, h3, l0, l1, l2, l3;
        split2(v[t].x, h0, l0); split2(v[t].y, h1, l1);
        split2(v[t].z, h2, l2); split2(v[t].w, h3, l3);
        ((uint2*)hi)[idx[t]] = make_uint2(packpair(h0, h1), packpair(h2, h3));
        ((uint2*)lo)[idx[t]] = make_uint2(packpair(l0, l1), packpair(l2, l3));
    }
}

// ---------------------------------------------------------------------------
// RoPE: fp32 in, bf16 hi/lo out; Q pre-scaled by 1/sqrt(128)
// ---------------------------------------------------------------------------
__global__ void rope_split() {
    long long idx = (long long)blockIdx.x * blockDim.x + threadIdx.x;
    const long long QP = (long long)S_LEN * HQ * 64;
    const long long KP = (long long)S_LEN * HKV * 64;
    if (idx >= QP + KP) return;

    const float* src; __nv_bfloat16 *dh, *dl;
    int s, h, i, stride; float postscale;
    if (idx < QP) {
        s = (int)(idx / (HQ * 64));
        int rem = (int)(idx % (HQ * 64));
        h = rem / 64; i = rem % 64;
        src = g_q; dh = g_qh; dl = g_ql; stride = DMODEL;
        postscale = 0.08838834764831845f;
    } else {
        long long t = idx - QP;
        s = (int)(t / (HKV * 64));
        int rem = (int)(t % (HKV * 64));
        h = rem / 64; i = rem % 64;
        src = g_k; dh = g_kh; dl = g_kl; stride = DKV;
        postscale = 1.0f;
    }

    float invf = (float)(1.0 / pow(10000.0, (double)i / 64.0));
    float ang = (float)s * invf;
    double sd, cd;
    sincos((double)ang, &sd, &cd);
    float c = (float)cd, sn = (float)sd;

    size_t off = (size_t)s * (size_t)stride + (size_t)h * HD + 2 * (size_t)i;
    float x1 = src[off], x2 = src[off + 1];
    float o1 = (x1 * c - x2 * sn) * postscale;
    float o2 = (x1 * sn + x2 * c) * postscale;
    __nv_bfloat16 h1, h2, l1, l2;
    split2(o1, h1, l1); split2(o2, h2, l2);
    *(uint32_t*)(dh + off) = packpair(h1, h2);
    *(uint32_t*)(dl + off) = packpair(l1, l2);
}

// ---------------------------------------------------------------------------
// Transpose V [s][d] -> Vt [d][s], bf16 hi/lo
// ---------------------------------------------------------------------------
__global__ void transpose_v_split() {
    __shared__ float t[32][33];
    int d0 = blockIdx.x * 32;
    int s0 = blockIdx.y * 32;
    for (int i = threadIdx.y; i < 32; i += 8)
        t[i][threadIdx.x] = g_v[(size_t)(s0 + i) * DKV + d0 + threadIdx.x];
    __syncthreads();
    for (int i = threadIdx.y; i < 32; i += 8) {
        float v = t[threadIdx.x][i];
        __nv_bfloat16 h, l;
        split2(v, h, l);
        size_t o = (size_t)(d0 + i) * S_LEN + s0 + threadIdx.x;
        g_vth[o] = h;
        g_vtl[o] = l;
    }
}

// ---------------------------------------------------------------------------
// Launch
// ---------------------------------------------------------------------------
extern "C" void kernel_launch(void* const* d_in, const int* in_sizes, int n_in,
                              void* d_out, int out_size)
{
    const float* x  = (const float*)d_in[0];
    const float* wq = (const float*)d_in[1];
    const float* wk = (const float*)d_in[2];
    const float* wv = (const float*)d_in[3];
    const float* wo = (const float*)d_in[4];
    float* out = (float*)d_out;

    __nv_bfloat16 *xh, *xl, *wqh, *wql, *wkh, *wkl, *wvh, *wvl, *woh, *wol, *ah, *al;
    cudaGetSymbolAddress((void**)&xh,  g_xh);  cudaGetSymbolAddress((void**)&xl,  g_xl);
    cudaGetSymbolAddress((void**)&wqh, g_wqh); cudaGetSymbolAddress((void**)&wql, g_wql);
    cudaGetSymbolAddress((void**)&wkh, g_wkh); cudaGetSymbolAddress((void**)&wkl, g_wkl);
    cudaGetSymbolAddress((void**)&wvh, g_wvh); cudaGetSymbolAddress((void**)&wvl, g_wvl);
    cudaGetSymbolAddress((void**)&woh, g_woh); cudaGetSymbolAddress((void**)&wol, g_wol);
    cudaGetSymbolAddress((void**)&ah,  g_ah);  cudaGetSymbolAddress((void**)&al,  g_al);

    cudaFuncSetAttribute(tcg_nt,
        cudaFuncAttributeMaxDynamicSharedMemorySize, GSMEM);
    cudaFuncSetAttribute(tcg_qkv,
        cudaFuncAttributeMaxDynamicSharedMemorySize, GSMEM);
    cudaFuncSetAttribute(flash_attn,
        cudaFuncAttributeMaxDynamicSharedMemorySize, FA_SMEM);

#define SPLIT(src, h, l, n) do {                                    \
    int n4 = (int)((n) / 4);                                        \
    int blocks = (n4 + 4 * 256 - 1) / (4 * 256);                    \
    split_f32<<<blocks, 256>>>(src, h, l, n4);                      \
} while (0)

    // 0) split inputs
    SPLIT(x,  xh,  xl,  (long long)S_LEN * DMODEL);
    SPLIT(wq, wqh, wql, (long long)DMODEL * DMODEL);
    SPLIT(wk, wkh, wkl, (long long)DKV * DMODEL);
    SPLIT(wv, wvh, wvl, (long long)DKV * DMODEL);
    SPLIT(wo, woh, wol, (long long)DMODEL * DMODEL);

    // 1) Merged Q/K/V projections
    tcg_qkv<<<dim3(48, 16), 256, GSMEM>>>();

    // 2) RoPE -> bf16 hi/lo Q (pre-scaled), K
    {
        long long total = (long long)S_LEN * HQ * 64 + (long long)S_LEN * HKV * 64;
        rope_split<<<(int)((total + 255) / 256), 256>>>();
    }

    // 3) V transpose -> bf16 hi/lo Vt
    transpose_v_split<<<dim3(DKV / 32, S_LEN / 32), dim3(32, 8)>>>();

    // 4) Fused attention -> g_ah/g_al
    flash_attn<<<dim3(S_LEN / 64, HQ), 128, FA_SMEM>>>();

    // 5) out = attn * wo^T
    tcg_nt<<<dim3(DMODEL / 128, S_LEN / 128), 256, GSMEM>>>(
        ah, al, woh, wol, out, DMODEL, DMODEL, DMODEL, DMODEL, 1.0f);
}